// round 4
// baseline (speedup 1.0000x reference)
#include <cuda_runtime.h>
#include <cuda_bf16.h>
#include <cstdint>

#define B_ROWS   65536
#define OUT_N    2048
#define IN_K     64
#define BM       128
#define BN       128
#define NTHREADS 256

// ---------------- scratch (__device__ globals: allocation-free) ----------------
// Distinct split tiles only: X chunks [Xh, Xl]; C chunks [Ch, Cl].
// Products computed: Ch*Xh + Cl*Xh + Ch*Xl  (drops 2nd-order Cl*Xl, ~1e-7)
__device__ __nv_bfloat16 g_X[2ull * B_ROWS * IN_K];
__device__ __nv_bfloat16 g_C[2ull * OUT_N * IN_K];
__device__ float g_x2[B_ROWS];
__device__ float g_c2[OUT_N];
__device__ float g_e2[OUT_N];      // -exp(-2*log_sigma) * log2(e)

// ---------------- PTX helpers (sm_80-era only; no 'a' features) ----------------
__device__ __forceinline__ uint32_t smem_u32(const void* p) {
    uint32_t a;
    asm("{ .reg .u64 t; cvta.to.shared.u64 t, %1; cvt.u32.u64 %0, t; }" : "=r"(a) : "l"(p));
    return a;
}
__device__ __forceinline__ void cp16(uint32_t s, const void* g) {
    asm volatile("{ .reg .u64 ga; cvta.to.global.u64 ga, %1; cp.async.cg.shared.global [%0], [ga], 16; }"
                 :: "r"(s), "l"(g) : "memory");
}
#define CP_COMMIT() asm volatile("cp.async.commit_group;" ::: "memory")
#define CP_WAIT0()  asm volatile("cp.async.wait_group 0;" ::: "memory")

#define LDSM4(r, a) \
    asm volatile("ldmatrix.sync.aligned.m8n8.x4.shared.b16 {%0,%1,%2,%3}, [%4];" \
        : "=r"((r)[0]), "=r"((r)[1]), "=r"((r)[2]), "=r"((r)[3]) : "r"(a))

#define MMA16816(d, a, b0, b1) \
    asm volatile("mma.sync.aligned.m16n8k16.row.col.f32.bf16.bf16.f32 " \
        "{%0,%1,%2,%3}, {%4,%5,%6,%7}, {%8,%9}, {%0,%1,%2,%3};" \
        : "+f"((d)[0]), "+f"((d)[1]), "+f"((d)[2]), "+f"((d)[3]) \
        : "r"((a)[0]), "r"((a)[1]), "r"((a)[2]), "r"((a)[3]), "r"(b0), "r"(b1))

// ---------------- merged prep: fp32 -> (hi, lo) bf16 split + norms ----------------
// blocks [0, 4096): input rows; blocks [4096, 4224): center rows.
__global__ void prep_all(const float* __restrict__ inp,
                         const float* __restrict__ cen,
                         const float* __restrict__ ls) {
    const int b = blockIdx.x;
    const bool is_c = (b >= 4096);
    const int g = (is_c ? (b - 4096) : b) * blockDim.x + threadIdx.x;
    const int row = g >> 4, seg = g & 15;

    const float* src = is_c ? cen : inp;
    const float4 v = *(const float4*)(src + (size_t)row * IN_K + seg * 4);
    float vv[4] = {v.x, v.y, v.z, v.w};
    float s = 0.f;
    __nv_bfloat16 h[4], l[4];
    #pragma unroll
    for (int i = 0; i < 4; i++) {
        s = fmaf(vv[i], vv[i], s);
        h[i] = __float2bfloat16(vv[i]);
        l[i] = __float2bfloat16(vv[i] - __bfloat162float(h[i]));
    }
    uint2 hp, lp;
    memcpy(&hp, h, 8); memcpy(&lp, l, 8);
    const size_t base = (size_t)row * IN_K + seg * 4;
    if (is_c) {
        const size_t CH = (size_t)OUT_N * IN_K;
        *(uint2*)(g_C + base)      = hp;   // chunk 0: Ch
        *(uint2*)(g_C + CH + base) = lp;   // chunk 1: Cl
    } else {
        const size_t CH = (size_t)B_ROWS * IN_K;
        *(uint2*)(g_X + base)      = hp;   // chunk 0: Xh
        *(uint2*)(g_X + CH + base) = lp;   // chunk 1: Xl
    }
    #pragma unroll
    for (int m = 1; m <= 8; m <<= 1) s += __shfl_xor_sync(~0u, s, m);
    if (seg == 0) {
        if (is_c) {
            g_c2[row] = s;
            g_e2[row] = -1.4426950408889634f * expf(-2.f * ls[row]);
        } else {
            g_x2[row] = s;
        }
    }
}

// ---------------- main: HMMA GEMM + fused gaussian epilogue ----------------
// smem per chunk tile: [128 rows][64 bf16] = 128 B/row, XOR-swizzled in 16B units.
extern __shared__ char smem_raw[];

__global__ __launch_bounds__(NTHREADS, 2)
void rbf_hmma(float* __restrict__ out) {
    __nv_bfloat16* sA = (__nv_bfloat16*)smem_raw;        // 2*128*64 bf16 = 32 KB
    __nv_bfloat16* sB = sA + 2 * BM * IN_K;              // 32 KB
    float* x2s = (float*)(sB + 2 * BN * IN_K);           // 128 f
    float* c2s = x2s + BM;                               // 128 f
    float* e2s = c2s + BN;                               // 128 f

    const int tid  = threadIdx.x;
    const int col0 = blockIdx.x * BN;    // fast dim -> L2 reuse of x tile
    const int row0 = blockIdx.y * BM;

    const uint32_t sAu = smem_u32(sA);
    const uint32_t sBu = smem_u32(sB);

    // ---- async tile loads: 2 chunks x [128][64] bf16 per side, swizzled ----
    #pragma unroll
    for (int i = 0; i < 8; i++) {
        int u = tid + i * NTHREADS;          // 0..2047
        int ch = u >> 10, rem = u & 1023;
        int r = rem >> 3, c = rem & 7;
        uint32_t so = ch * 16384 + r * 128 + ((c ^ (r & 7)) << 4);
        cp16(sAu + so, g_X + (size_t)ch * (B_ROWS * IN_K) + (size_t)(row0 + r) * IN_K + c * 8);
        cp16(sBu + so, g_C + (size_t)ch * (OUT_N * IN_K) + (size_t)(col0 + r) * IN_K + c * 8);
    }
    CP_COMMIT();

    if (tid < BM) {
        x2s[tid] = g_x2[row0 + tid];
    } else {
        int c = tid - BM;
        c2s[c] = g_c2[col0 + c];
        e2s[c] = g_e2[col0 + c];
    }
    CP_WAIT0();
    __syncthreads();

    // ---- warp tiling: 8 warps = 4 (M) x 2 (N); warp tile 32x64 ----
    const int l   = tid & 31;
    const int wid = tid >> 5;
    const int wr  = wid & 3;       // m: wr*32
    const int wc  = wid >> 2;      // n: wc*64

    // ldmatrix lane base addresses (within one chunk), XOR'd by k-step later
    uint32_t abase[2];
    {
        int hb = l >> 4;                       // k-half select
        #pragma unroll
        for (int mi = 0; mi < 2; mi++) {
            int row = wr * 32 + mi * 16 + (l & 15);
            abase[mi] = row * 128 + ((hb ^ (row & 7)) << 4);
        }
    }
    uint32_t bbase[4];
    {
        int m = l >> 3;                        // matrix index within x4
        int hb = m & 1;
        #pragma unroll
        for (int q = 0; q < 4; q++) {
            int n = wc * 64 + (2 * q + (m >> 1)) * 8 + (l & 7);
            bbase[q] = n * 128 + ((hb ^ (n & 7)) << 4);
        }
    }

    float acc[2][8][4];
    #pragma unroll
    for (int mi = 0; mi < 2; mi++)
        #pragma unroll
        for (int j = 0; j < 8; j++)
            #pragma unroll
            for (int q = 0; q < 4; q++) acc[mi][j][q] = 0.f;

    // 12 k16 steps = 3 chunk-pair phases x 4 steps:
    //   phase 0: A=Xh (chunk 0), B=Ch (chunk 0)
    //   phase 1: A=Xh (chunk 0), B=Cl (chunk 1)
    //   phase 2: A=Xl (chunk 1), B=Ch (chunk 0)
    #pragma unroll
    for (int ks = 0; ks < 12; ks++) {
        const int ph = ks >> 2;
        const uint32_t coA = (ph == 2) ? 16384u : 0u;
        const uint32_t coB = (ph == 1) ? 16384u : 0u;
        const uint32_t kx = (uint32_t)(ks & 3) << 5; // XOR in swizzled 16B-unit space

        uint32_t a[2][4], b[4][4];
        LDSM4(a[0], sAu + coA + (abase[0] ^ kx));
        LDSM4(a[1], sAu + coA + (abase[1] ^ kx));
        LDSM4(b[0], sBu + coB + (bbase[0] ^ kx));
        LDSM4(b[1], sBu + coB + (bbase[1] ^ kx));
        LDSM4(b[2], sBu + coB + (bbase[2] ^ kx));
        LDSM4(b[3], sBu + coB + (bbase[3] ^ kx));

        #pragma unroll
        for (int j = 0; j < 8; j++) {
            uint32_t b0 = b[j >> 1][(j & 1) * 2];
            uint32_t b1 = b[j >> 1][(j & 1) * 2 + 1];
            MMA16816(acc[0][j], a[0], b0, b1);
            MMA16816(acc[1][j], a[1], b0, b1);
        }
    }

    // ---- epilogue: out = exp2((x2 - 2*dot + c2) * e2), e2 = -log2e/sigma^2 ----
    #pragma unroll
    for (int mi = 0; mi < 2; mi++) {
        const int rl = wr * 32 + mi * 16 + (l >> 2);
        const float x2a = x2s[rl];
        const float x2b = x2s[rl + 8];
        float* o0 = out + (size_t)(row0 + rl) * OUT_N + col0;
        float* o1 = o0 + 8 * OUT_N;
        #pragma unroll
        for (int j = 0; j < 8; j++) {
            const int c = wc * 64 + j * 8 + 2 * (l & 3);
            const float c20 = c2s[c],  c21 = c2s[c + 1];
            const float e0  = e2s[c],  e1  = e2s[c + 1];
            const float* A  = acc[mi][j];
            float s0 = fmaxf(fmaf(-2.f, A[0], x2a + c20), 0.f);
            float s1 = fmaxf(fmaf(-2.f, A[1], x2a + c21), 0.f);
            float s2 = fmaxf(fmaf(-2.f, A[2], x2b + c20), 0.f);
            float s3 = fmaxf(fmaf(-2.f, A[3], x2b + c21), 0.f);
            float2 v0 = make_float2(exp2f(s0 * e0), exp2f(s1 * e1));
            float2 v1 = make_float2(exp2f(s2 * e0), exp2f(s3 * e1));
            *(float2*)(o0 + c) = v0;
            *(float2*)(o1 + c) = v1;
        }
    }
}

extern "C" void kernel_launch(void* const* d_in, const int* in_sizes, int n_in,
                              void* d_out, int out_size) {
    (void)in_sizes; (void)n_in; (void)out_size;
    const float* input      = (const float*)d_in[0];
    const float* centers    = (const float*)d_in[1];
    const float* log_sigmas = (const float*)d_in[2];
    float* out              = (float*)d_out;

    const int smem_bytes = 2 * BM * IN_K * 2 + 2 * BN * IN_K * 2
                         + (BM + 2 * BN) * (int)sizeof(float);  // 67072 B
    cudaFuncSetAttribute(rbf_hmma, cudaFuncAttributeMaxDynamicSharedMemorySize, smem_bytes);

    prep_all<<<B_ROWS * 16 / 256 + OUT_N * 16 / 256, 256>>>(input, centers, log_sigmas);
    rbf_hmma<<<dim3(OUT_N / BN, B_ROWS / BM), NTHREADS, smem_bytes>>>(out);
}